// round 4
// baseline (speedup 1.0000x reference)
#include <cuda_runtime.h>
#include <cstdint>

#define NNODES 100000
#define MHE    200000
#define NEDGE  2000000
#define INF_   16
#define HIDF   64
#define XP 132

typedef unsigned long long ull;

// ---------------- scratch (static __device__) ----------------
static __device__ __align__(16) float4 g_she[2 * MHE * 4];      // [t][he][16] as float4[4]
static __device__ __align__(16) float4 g_agg[2 * NNODES * 4];   // [t][n][16]  as float4[4]
static __device__ __align__(16) float  g_bdeg[2 * MHE];         // counts
static __device__ __align__(16) float  g_ddeg[2 * NNODES];      // counts
static __device__ __align__(16) float  g_Wcm[2 * INF_ * HIDF];  // W_conv[t] @ W_mix_t
static __device__ __align__(16) float  g_bprime[HIDF];
static __device__ __align__(16) float  g_Wr[128 * 64];
static __device__ __align__(16) float  g_Wz[128 * 64];
static __device__ __align__(16) float  g_Wni[64 * 64];
static __device__ __align__(16) float  g_Wnh[64 * 64];
static __device__ __align__(16) float  g_br[64], g_bz[64], g_bni[64], g_bnh[64];

// ---------------- helpers ----------------
__device__ __forceinline__ void red4(float4* addr, float4 v) {
    asm volatile("red.global.add.v4.f32 [%0], {%1,%2,%3,%4};"
                 :: "l"(addr), "f"(v.x), "f"(v.y), "f"(v.z), "f"(v.w) : "memory");
}
__device__ __forceinline__ void red1(float* addr, float v) {
    asm volatile("red.global.add.f32 [%0], %1;" :: "l"(addr), "f"(v) : "memory");
}
__device__ __forceinline__ ull pk2(float lo, float hi) {
    ull r; asm("mov.b64 %0,{%1,%2};" : "=l"(r) : "f"(lo), "f"(hi)); return r;
}
__device__ __forceinline__ float2 up2(ull v) {
    float2 r; asm("mov.b64 {%0,%1},%2;" : "=f"(r.x), "=f"(r.y) : "l"(v)); return r;
}
__device__ __forceinline__ ull f2fma(ull a, ull b, ull c) {
    ull d; asm("fma.rn.f32x2 %0,%1,%2,%3;" : "=l"(d) : "l"(a), "l"(b), "l"(c)); return d;
}
__device__ __forceinline__ float sigf(float x) {
    float e = __expf(-x);
    return __fdividef(1.f, 1.f + e);
}
__device__ __forceinline__ float tanhfast(float x) {
    float e = __expf(-2.f * x);
    return __fdividef(1.f - e, 1.f + e);
}

// ---------------- kernel 1: zero scratch + precompute weights ----------------
__global__ void k_pre(const float* __restrict__ Wc, const float* __restrict__ bc,
                      const float* __restrict__ Wm, const float* __restrict__ bm,
                      const float* __restrict__ Wih, const float* __restrict__ Whh,
                      const float* __restrict__ bih, const float* __restrict__ bhh) {
    int i = blockIdx.x * 256 + threadIdx.x;
    float4 z = make_float4(0.f, 0.f, 0.f, 0.f);
    if (i < 1600000) { g_she[i] = z; return; }
    int j = i - 1600000;
    if (j < 800000) { g_agg[j] = z; return; }
    int k = i - 2400000;
    if (k >= 0 && k < 100000) { ((float4*)g_bdeg)[k] = z; return; }
    int l = i - 2500000;
    if (l >= 0 && l < 50000) { ((float4*)g_ddeg)[l] = z; return; }
    int m = i - 2550000;
    if (m >= 0 && m < 2112) {
        if (m < 2048) {
            int t = m >> 10, rem = m & 1023, ii = rem >> 6, jj = rem & 63;
            float acc = 0.f;
            for (int kk = 0; kk < 64; kk++)
                acc += Wc[(t * 16 + ii) * 64 + kk] * Wm[(t * 64 + kk) * 64 + jj];
            g_Wcm[m] = acc;
        } else {
            int jj = m - 2048;
            float acc = bm[jj];
            for (int t = 0; t < 2; t++)
                for (int kk = 0; kk < 64; kk++)
                    acc += bc[t * 64 + kk] * Wm[(t * 64 + kk) * 64 + jj];
            g_bprime[jj] = acc;
        }
        return;
    }
    int p = i - 2552112;
    if (p >= 0 && p < 8192) {
        int kk = p >> 6, jj = p & 63;
        g_Wr[p] = (kk < 64) ? Wih[jj * 64 + kk]        : Whh[jj * 64 + (kk - 64)];
        g_Wz[p] = (kk < 64) ? Wih[(64 + jj) * 64 + kk] : Whh[(64 + jj) * 64 + (kk - 64)];
        if (kk < 64) {
            g_Wni[p] = Wih[(128 + jj) * 64 + kk];
            g_Wnh[p] = Whh[(128 + jj) * 64 + kk];
        }
        if (p < 64) {
            g_br[p]  = bih[p] + bhh[p];
            g_bz[p]  = bih[64 + p] + bhh[64 + p];
            g_bni[p] = bih[128 + p];
            g_bnh[p] = bhh[128 + p];
        }
    }
}

// ---------------- kernel 2: scatter x -> hyperedges + degree counts ----------------
__global__ void k_scat1(const int* __restrict__ en, const int* __restrict__ eh,
                        const int* __restrict__ ea, const float4* __restrict__ x4) {
    int gid = blockIdx.x * 256 + threadIdx.x;
    int e = gid >> 2;
    if (e >= NEDGE) return;
    int sub = gid & 3;
    int node = __ldg(en + e), he = __ldg(eh + e), t = __ldg(ea + e);
    float4 v = x4[node * 4 + sub];
    red4(&g_she[(t * MHE + he) * 4 + sub], v);
    if (sub == 0) red1(&g_bdeg[t * MHE + he], 1.f);
    else if (sub == 1) red1(&g_ddeg[t * NNODES + node], 1.f);
}

// ---------------- kernel 3: hyperedges -> nodes (Binv on the fly) ----------------
__global__ void k_scat2(const int* __restrict__ en, const int* __restrict__ eh,
                        const int* __restrict__ ea) {
    int gid = blockIdx.x * 256 + threadIdx.x;
    int e = gid >> 2;
    if (e >= NEDGE) return;
    int sub = gid & 3;
    int node = __ldg(en + e), he = __ldg(eh + e), t = __ldg(ea + e);
    float c = __ldg(&g_bdeg[t * MHE + he]);   // >= 1 for this edge's own key
    float bi = 1.0f / c;
    float4 v = g_she[(t * MHE + he) * 4 + sub];
    v.x *= bi; v.y *= bi; v.z *= bi; v.w *= bi;
    red4(&g_agg[(t * NNODES + node) * 4 + sub], v);
}

// ---------------- kernel 4: fused mix + GRU + pred ----------------
// 128 nodes/block, 512 threads (16 warps); per-thread tile = 2 nodes x 8 gate-outputs.
__global__ __launch_bounds__(512, 1) void k_gru(const float* __restrict__ hprev,
                                                const float* __restrict__ Wout,
                                                const float* __restrict__ bout,
                                                float* __restrict__ out, int Nn) {
    extern __shared__ float sm[];
    float* Xs  = sm;                  // [128][XP]: cols 0..63 = H, 64..127 = h_prev
    float* Wr  = sm + 128 * XP;
    float* Wz  = Wr + 8192;
    float* Wni = Wz + 8192;
    float* Wnh = Wni + 4096;
    float* Wcm = Wnh + 4096;          // 2048
    float* br  = Wcm + 2048;
    float* bz  = br + 64;
    float* bni = bz + 64;
    float* bnh = bni + 64;
    float* bp  = bnh + 64;            // 64
    float* wo  = bp + 64;             // 192 (W_out transposed, [j*3+c])
    const int tid = threadIdx.x;

    for (int i = tid; i < 2048; i += 512) {
        ((float4*)Wr)[i] = ((const float4*)g_Wr)[i];
        ((float4*)Wz)[i] = ((const float4*)g_Wz)[i];
    }
    for (int i = tid; i < 1024; i += 512) {
        ((float4*)Wni)[i] = ((const float4*)g_Wni)[i];
        ((float4*)Wnh)[i] = ((const float4*)g_Wnh)[i];
    }
    if (tid < 512) { int i = tid; if (i < 512) ((float4*)Wcm)[i] = ((const float4*)g_Wcm)[i]; }
    if (tid < 64) { br[tid] = g_br[tid]; bz[tid] = g_bz[tid];
                    bni[tid] = g_bni[tid]; bnh[tid] = g_bnh[tid]; bp[tid] = g_bprime[tid]; }
    if (tid >= 256 && tid < 448) { int q = tid - 256; int j = q / 3, c = q % 3; wo[q] = Wout[j * 64 + c]; }

    const int nbase = blockIdx.x * 128;
    // stage h_prev into Xs cols 64..127
    for (int fl = tid; fl < 128 * 16; fl += 512) {
        int n = fl >> 4, q = fl & 15;
        int gn = nbase + n;
        float4 v = make_float4(0.f, 0.f, 0.f, 0.f);
        if (gn < Nn) v = ((const float4*)hprev)[gn * 16 + q];
        *(float4*)&Xs[n * XP + 64 + q * 4] = v;
    }

    const int ng = tid >> 3;          // 0..63
    const int jg = tid & 7;           // 0..7
    const int j0 = jg * 8;

    // ---- mix: H[row][j0..j0+7] for this thread's 2 nodes ----
    for (int n = 0; n < 2; n++) {
        int row = ng * 2 + n;
        int gn = nbase + row;
        float a[32];
        if (gn < Nn) {
            float c0 = __ldg(&g_ddeg[gn]), c1 = __ldg(&g_ddeg[NNODES + gn]);
            float d0 = (c0 > 0.f) ? 1.f / c0 : 0.f;
            float d1 = (c1 > 0.f) ? 1.f / c1 : 0.f;
#pragma unroll
            for (int q = 0; q < 4; q++) {
                float4 v = g_agg[(size_t)gn * 4 + q];
                a[q * 4 + 0] = v.x * d0; a[q * 4 + 1] = v.y * d0;
                a[q * 4 + 2] = v.z * d0; a[q * 4 + 3] = v.w * d0;
                float4 w = g_agg[(size_t)(NNODES + gn) * 4 + q];
                a[16 + q * 4 + 0] = w.x * d1; a[16 + q * 4 + 1] = w.y * d1;
                a[16 + q * 4 + 2] = w.z * d1; a[16 + q * 4 + 3] = w.w * d1;
            }
        } else {
#pragma unroll
            for (int q = 0; q < 32; q++) a[q] = 0.f;
        }
        float acc[8];
#pragma unroll
        for (int s = 0; s < 8; s++) acc[s] = bp[j0 + s];
#pragma unroll
        for (int i = 0; i < 16; i++) {
            float a0 = a[i], a1 = a[16 + i];
            const float* w0 = &Wcm[i * 64 + j0];
            const float* w1 = &Wcm[1024 + i * 64 + j0];
#pragma unroll
            for (int s = 0; s < 8; s++) acc[s] += a0 * w0[s] + a1 * w1[s];
        }
#pragma unroll
        for (int s = 0; s < 8; s++) acc[s] = fmaxf(acc[s], 0.f);
        *(float4*)&Xs[row * XP + j0]     = make_float4(acc[0], acc[1], acc[2], acc[3]);
        *(float4*)&Xs[row * XP + j0 + 4] = make_float4(acc[4], acc[5], acc[6], acc[7]);
    }
    __syncthreads();

    const float* Xb = &Xs[(ng * 2) * XP];

    // ---- pass 1: r,z over concat [H ; h_prev] ----
    ull ar[8], az[8];
#pragma unroll
    for (int jj = 0; jj < 4; jj++) {
        ull b_r = pk2(br[j0 + 2 * jj], br[j0 + 2 * jj + 1]);
        ull b_z = pk2(bz[j0 + 2 * jj], bz[j0 + 2 * jj + 1]);
#pragma unroll
        for (int n = 0; n < 2; n++) { ar[n * 4 + jj] = b_r; az[n * 4 + jj] = b_z; }
    }
#pragma unroll 4
    for (int k = 0; k < 128; k++) {
        float x0 = Xb[k], x1 = Xb[XP + k];
        ull xx[2] = { pk2(x0, x0), pk2(x1, x1) };
        ulonglong2 wra = *(const ulonglong2*)&Wr[k * 64 + j0];
        ulonglong2 wrb = *(const ulonglong2*)&Wr[k * 64 + j0 + 4];
        ulonglong2 wza = *(const ulonglong2*)&Wz[k * 64 + j0];
        ulonglong2 wzb = *(const ulonglong2*)&Wz[k * 64 + j0 + 4];
#pragma unroll
        for (int n = 0; n < 2; n++) {
            ar[n * 4 + 0] = f2fma(xx[n], wra.x, ar[n * 4 + 0]);
            ar[n * 4 + 1] = f2fma(xx[n], wra.y, ar[n * 4 + 1]);
            ar[n * 4 + 2] = f2fma(xx[n], wrb.x, ar[n * 4 + 2]);
            ar[n * 4 + 3] = f2fma(xx[n], wrb.y, ar[n * 4 + 3]);
            az[n * 4 + 0] = f2fma(xx[n], wza.x, az[n * 4 + 0]);
            az[n * 4 + 1] = f2fma(xx[n], wza.y, az[n * 4 + 1]);
            az[n * 4 + 2] = f2fma(xx[n], wzb.x, az[n * 4 + 2]);
            az[n * 4 + 3] = f2fma(xx[n], wzb.y, az[n * 4 + 3]);
        }
    }
    // ---- pass 2: i_n over H, h_n over h_prev ----
    ull ani[8], anh[8];
#pragma unroll
    for (int jj = 0; jj < 4; jj++) {
        ull b_i = pk2(bni[j0 + 2 * jj], bni[j0 + 2 * jj + 1]);
        ull b_h = pk2(bnh[j0 + 2 * jj], bnh[j0 + 2 * jj + 1]);
#pragma unroll
        for (int n = 0; n < 2; n++) { ani[n * 4 + jj] = b_i; anh[n * 4 + jj] = b_h; }
    }
#pragma unroll 4
    for (int k = 0; k < 64; k++) {
        float h0 = Xb[k], h1 = Xb[XP + k];
        float p0 = Xb[64 + k], p1 = Xb[XP + 64 + k];
        ull xh[2] = { pk2(h0, h0), pk2(h1, h1) };
        ull xp[2] = { pk2(p0, p0), pk2(p1, p1) };
        ulonglong2 wia = *(const ulonglong2*)&Wni[k * 64 + j0];
        ulonglong2 wib = *(const ulonglong2*)&Wni[k * 64 + j0 + 4];
        ulonglong2 wha = *(const ulonglong2*)&Wnh[k * 64 + j0];
        ulonglong2 whb = *(const ulonglong2*)&Wnh[k * 64 + j0 + 4];
#pragma unroll
        for (int n = 0; n < 2; n++) {
            ani[n * 4 + 0] = f2fma(xh[n], wia.x, ani[n * 4 + 0]);
            ani[n * 4 + 1] = f2fma(xh[n], wia.y, ani[n * 4 + 1]);
            ani[n * 4 + 2] = f2fma(xh[n], wib.x, ani[n * 4 + 2]);
            ani[n * 4 + 3] = f2fma(xh[n], wib.y, ani[n * 4 + 3]);
            anh[n * 4 + 0] = f2fma(xp[n], wha.x, anh[n * 4 + 0]);
            anh[n * 4 + 1] = f2fma(xp[n], wha.y, anh[n * 4 + 1]);
            anh[n * 4 + 2] = f2fma(xp[n], whb.x, anh[n * 4 + 2]);
            anh[n * 4 + 3] = f2fma(xp[n], whb.y, anh[n * 4 + 3]);
        }
    }

    // ---- combine + stores + fused pred (shfl reduce over the 8 jg lanes) ----
    float bo0 = __ldg(bout + 0), bo1 = __ldg(bout + 1), bo2 = __ldg(bout + 2);
#pragma unroll
    for (int n = 0; n < 2; n++) {
        int gn = nbase + ng * 2 + n;
        float res[8];
#pragma unroll
        for (int jj = 0; jj < 4; jj++) {
            float2 rr = up2(ar[n * 4 + jj]);
            float2 zz = up2(az[n * 4 + jj]);
            float2 vi = up2(ani[n * 4 + jj]);
            float2 vh = up2(anh[n * 4 + jj]);
#pragma unroll
            for (int s = 0; s < 2; s++) {
                float r = sigf(s ? rr.y : rr.x);
                float z = sigf(s ? zz.y : zz.x);
                float nn = tanhfast((s ? vi.y : vi.x) + r * (s ? vh.y : vh.x));
                float hp = Xb[n * XP + 64 + j0 + jj * 2 + s];
                res[jj * 2 + s] = (1.f - z) * nn + z * hp;
            }
        }
        if (gn < Nn) {
            float4* o = (float4*)&out[(size_t)gn * 64 + j0];
            o[0] = make_float4(res[0], res[1], res[2], res[3]);
            o[1] = make_float4(res[4], res[5], res[6], res[7]);
        }
        float p0 = 0.f, p1 = 0.f, p2 = 0.f;
#pragma unroll
        for (int s = 0; s < 8; s++) {
            float hv = res[s];
            int j = j0 + s;
            p0 += hv * wo[j * 3 + 0];
            p1 += hv * wo[j * 3 + 1];
            p2 += hv * wo[j * 3 + 2];
        }
#pragma unroll
        for (int m = 1; m < 8; m <<= 1) {
            p0 += __shfl_xor_sync(0xffffffffu, p0, m);
            p1 += __shfl_xor_sync(0xffffffffu, p1, m);
            p2 += __shfl_xor_sync(0xffffffffu, p2, m);
        }
        if (jg == 0 && gn < Nn) {
            float* pp = out + (size_t)Nn * 64 + (size_t)gn * 3;
            pp[0] = p0 + bo0; pp[1] = p1 + bo1; pp[2] = p2 + bo2;
        }
    }
}

// ---------------- launch ----------------
extern "C" void kernel_launch(void* const* d_in, const int* in_sizes, int n_in,
                              void* d_out, int out_size) {
    const float* x     = (const float*)d_in[0];
    const float* hprev = (const float*)d_in[1];
    const int*   en    = (const int*)d_in[2];
    const int*   eh    = (const int*)d_in[3];
    const int*   ea    = (const int*)d_in[4];
    const float* Wconv = (const float*)d_in[5];
    const float* bconv = (const float*)d_in[6];
    const float* Wmix  = (const float*)d_in[7];
    const float* bmix  = (const float*)d_in[8];
    const float* Wih   = (const float*)d_in[9];
    const float* Whh   = (const float*)d_in[10];
    const float* bih   = (const float*)d_in[11];
    const float* bhh   = (const float*)d_in[12];
    const float* Wout  = (const float*)d_in[13];
    const float* bout  = (const float*)d_in[14];
    float* out = (float*)d_out;

    (void)in_sizes; (void)n_in; (void)out_size;

    k_pre<<<10002, 256>>>(Wconv, bconv, Wmix, bmix, Wih, Whh, bih, bhh);
    k_scat1<<<31250, 256>>>(en, eh, ea, (const float4*)x);
    k_scat2<<<31250, 256>>>(en, eh, ea);

    const int smem = (128 * XP + 8192 * 2 + 4096 * 2 + 2048 + 64 * 5 + 192) * 4;
    cudaFuncSetAttribute(k_gru, cudaFuncAttributeMaxDynamicSharedMemorySize, smem);
    k_gru<<<782, 512, smem>>>(hprev, Wout, bout, out, NNODES);
}

// round 6
// speedup vs baseline: 2.3027x; 2.3027x over previous
#include <cuda_runtime.h>
#include <cuda_bf16.h>
#include <cstdint>

#define NNODES 100000
#define MHE    200000
#define NEDGE  2000000

#define SA 136              // padded row stride (bf16 elems) for A and B tiles

// ---------------- scratch (static __device__) ----------------
static __device__ __align__(16) float4 g_she[2 * MHE * 4];
static __device__ __align__(16) float4 g_agg[2 * NNODES * 4];
static __device__ __align__(16) float  g_bdeg[2 * MHE];
static __device__ __align__(16) float  g_ddeg[2 * NNODES];
static __device__ __align__(16) float  g_Wcm[2048];              // [32][64]
static __device__ __align__(16) float  g_bprime[64];
static __device__ __align__(16) __nv_bfloat16 g_Bh[256 * SA];    // B hi, padded row-major [n][k]
static __device__ __align__(16) __nv_bfloat16 g_Bl[256 * SA];    // B lo
static __device__ __align__(16) float  g_br[64], g_bz[64], g_bni[64], g_bnh[64];

// smem byte offsets for k_gru
#define A_HI_OFF   0                 // 128*SA*2 = 34816
#define A_LO_OFF   34816
#define B_HI_OFF   69632             // 256*SA*2 = 69632
#define B_LO_OFF   139264
#define WCM_OFF    208896            // 8192
#define BR_OFF     217088
#define BZ_OFF     217344
#define BNI_OFF    217600
#define BNH_OFF    217856
#define BP_OFF     218112
#define WO_OFF     218368            // 768
#define SMEM_TOTAL 219136

// ---------------- helpers ----------------
__device__ __forceinline__ void red4(float4* addr, float4 v) {
    asm volatile("red.global.add.v4.f32 [%0], {%1,%2,%3,%4};"
                 :: "l"(addr), "f"(v.x), "f"(v.y), "f"(v.z), "f"(v.w) : "memory");
}
__device__ __forceinline__ void red1(float* addr, float v) {
    asm volatile("red.global.add.f32 [%0], %1;" :: "l"(addr), "f"(v) : "memory");
}
__device__ __forceinline__ float sigf(float x) {
    float e = __expf(-x);
    return __fdividef(1.f, 1.f + e);
}
__device__ __forceinline__ float tanhfast(float x) {
    float e = __expf(-2.f * x);
    return __fdividef(1.f - e, 1.f + e);
}
__device__ __forceinline__ uint32_t smem_u32(const void* p) {
    uint32_t a;
    asm("{ .reg .u64 t; cvta.to.shared.u64 t, %1; cvt.u32.u64 %0, t; }" : "=r"(a) : "l"(p));
    return a;
}
__device__ __forceinline__ void ldsm4(uint32_t& r0, uint32_t& r1, uint32_t& r2, uint32_t& r3,
                                      uint32_t addr) {
    asm volatile("ldmatrix.sync.aligned.m8n8.x4.shared.b16 {%0,%1,%2,%3}, [%4];"
                 : "=r"(r0), "=r"(r1), "=r"(r2), "=r"(r3) : "r"(addr));
}
__device__ __forceinline__ void ldsm2(uint32_t& r0, uint32_t& r1, uint32_t addr) {
    asm volatile("ldmatrix.sync.aligned.m8n8.x2.shared.b16 {%0,%1}, [%2];"
                 : "=r"(r0), "=r"(r1) : "r"(addr));
}
__device__ __forceinline__ void mma16816(float* c, uint32_t a0, uint32_t a1, uint32_t a2,
                                         uint32_t a3, uint32_t b0, uint32_t b1) {
    asm volatile("mma.sync.aligned.m16n8k16.row.col.f32.bf16.bf16.f32 "
                 "{%0,%1,%2,%3}, {%4,%5,%6,%7}, {%8,%9}, {%0,%1,%2,%3};"
                 : "+f"(c[0]), "+f"(c[1]), "+f"(c[2]), "+f"(c[3])
                 : "r"(a0), "r"(a1), "r"(a2), "r"(a3), "r"(b0), "r"(b1));
}
// write bf16 hi/lo pair (cols col,col+1; col even) into A tiles, padded row-major
__device__ __forceinline__ void write_a(char* smem, int row, int col, float v0, float v1) {
    __nv_bfloat16 h0 = __float2bfloat16(v0);
    __nv_bfloat16 h1 = __float2bfloat16(v1);
    __nv_bfloat16 l0 = __float2bfloat16(v0 - __bfloat162float(h0));
    __nv_bfloat16 l1 = __float2bfloat16(v1 - __bfloat162float(h1));
    uint32_t byte = (uint32_t)row * (SA * 2) + (uint32_t)col * 2;
    uint32_t hi = (uint32_t)__bfloat16_as_ushort(h0) | ((uint32_t)__bfloat16_as_ushort(h1) << 16);
    uint32_t lo = (uint32_t)__bfloat16_as_ushort(l0) | ((uint32_t)__bfloat16_as_ushort(l1) << 16);
    *(uint32_t*)(smem + A_HI_OFF + byte) = hi;
    *(uint32_t*)(smem + A_LO_OFF + byte) = lo;
}

// ---------------- kernel 1: zero scratch + precompute all weights ----------------
__global__ void k_pre(const float* __restrict__ Wc, const float* __restrict__ bc,
                      const float* __restrict__ Wm, const float* __restrict__ bm,
                      const float* __restrict__ Wih, const float* __restrict__ Whh,
                      const float* __restrict__ bih, const float* __restrict__ bhh) {
    int i = blockIdx.x * 256 + threadIdx.x;
    float4 z = make_float4(0.f, 0.f, 0.f, 0.f);
    if (i < 1600000) { g_she[i] = z; return; }
    int j = i - 1600000;
    if (j < 800000) { g_agg[j] = z; return; }
    int k = i - 2400000;
    if (k >= 0 && k < 100000) { ((float4*)g_bdeg)[k] = z; return; }
    int l = i - 2500000;
    if (l >= 0 && l < 50000) { ((float4*)g_ddeg)[l] = z; return; }
    int m = i - 2550000;
    if (m >= 0 && m < 2112) {
        if (m < 2048) {
            int t = m >> 10, rem = m & 1023, ii = rem >> 6, jj = rem & 63;
            float acc = 0.f;
            for (int kk = 0; kk < 64; kk++)
                acc += Wc[(t * 16 + ii) * 64 + kk] * Wm[(t * 64 + kk) * 64 + jj];
            g_Wcm[m] = acc;
        } else {
            int jj = m - 2048;
            float acc = bm[jj];
            for (int t = 0; t < 2; t++)
                for (int kk = 0; kk < 64; kk++)
                    acc += bc[t * 64 + kk] * Wm[(t * 64 + kk) * 64 + jj];
            g_bprime[jj] = acc;
        }
        return;
    }
    int p = i - 2552112;
    if (p >= 0 && p < 32768) {
        // B[n][k]: n = gate col (0..255), k = input (0..127).
        // n 0-63: r | 64-127: z | 128-191: i_n (H only) | 192-255: h_n (hprev only)
        int n = p >> 7, kk = p & 127;
        float w = 0.f;
        if (kk < 64) {
            if (n < 192) w = Wih[n * 64 + kk];
        } else {
            if (n < 128) w = Whh[n * 64 + (kk - 64)];
            else if (n >= 192) w = Whh[(n - 64) * 64 + (kk - 64)];
        }
        __nv_bfloat16 hi = __float2bfloat16(w);
        __nv_bfloat16 lo = __float2bfloat16(w - __bfloat162float(hi));
        g_Bh[n * SA + kk] = hi;
        g_Bl[n * SA + kk] = lo;
        if (p < 64) {
            g_br[p]  = bih[p] + bhh[p];
            g_bz[p]  = bih[64 + p] + bhh[64 + p];
            g_bni[p] = bih[128 + p];
            g_bnh[p] = bhh[128 + p];
        }
    }
}

// ---------------- kernel 2: scatter x -> hyperedges + degree counts ----------------
__global__ void k_scat1(const int* __restrict__ en, const int* __restrict__ eh,
                        const int* __restrict__ ea, const float4* __restrict__ x4) {
    int gid = blockIdx.x * 256 + threadIdx.x;
    int e = gid >> 2;
    if (e >= NEDGE) return;
    int sub = gid & 3;
    int node = __ldg(en + e), he = __ldg(eh + e), t = __ldg(ea + e);
    float4 v = x4[node * 4 + sub];
    red4(&g_she[(t * MHE + he) * 4 + sub], v);
    if (sub == 0) red1(&g_bdeg[t * MHE + he], 1.f);
    else if (sub == 1) red1(&g_ddeg[t * NNODES + node], 1.f);
}

// ---------------- kernel 3: hyperedges -> nodes ----------------
__global__ void k_scat2(const int* __restrict__ en, const int* __restrict__ eh,
                        const int* __restrict__ ea) {
    int gid = blockIdx.x * 256 + threadIdx.x;
    int e = gid >> 2;
    if (e >= NEDGE) return;
    int sub = gid & 3;
    int node = __ldg(en + e), he = __ldg(eh + e), t = __ldg(ea + e);
    float c = __ldg(&g_bdeg[t * MHE + he]);
    float bi = 1.0f / c;
    float4 v = g_she[(t * MHE + he) * 4 + sub];
    v.x *= bi; v.y *= bi; v.z *= bi; v.w *= bi;
    red4(&g_agg[(t * NNODES + node) * 4 + sub], v);
}

// ---------------- kernel 4: persistent HMMA mix+GRU+pred ----------------
// 148 CTAs x 256 threads (8 warps). Per 128-node tile:
//   stage A (mix + bf16 hi/lo split) -> mma.sync 3-term bf16 GEMM (regs) -> epilogue.
__global__ __launch_bounds__(256, 1) void k_gru(const float* __restrict__ hprev,
                                                const float* __restrict__ Wout,
                                                const float* __restrict__ bout,
                                                float* __restrict__ out, int Nn) {
    extern __shared__ char smem[];
    const uint32_t sbase = smem_u32(smem);
    const int tid = threadIdx.x;
    const int wid = tid >> 5;
    const int lane = tid & 31;

    // ---- stage constants once per CTA ----
    {
        const uint4* bh = reinterpret_cast<const uint4*>(g_Bh);
        const uint4* bl = reinterpret_cast<const uint4*>(g_Bl);
        uint4* sbh = reinterpret_cast<uint4*>(smem + B_HI_OFF);
        uint4* sbl = reinterpret_cast<uint4*>(smem + B_LO_OFF);
        for (int i = tid; i < 4352; i += 256) { sbh[i] = bh[i]; sbl[i] = bl[i]; }
        float4* swc = reinterpret_cast<float4*>(smem + WCM_OFF);
        const float4* gwc = reinterpret_cast<const float4*>(g_Wcm);
        for (int i = tid; i < 512; i += 256) swc[i] = gwc[i];
        if (tid < 64) {
            ((float*)(smem + BR_OFF))[tid]  = g_br[tid];
            ((float*)(smem + BZ_OFF))[tid]  = g_bz[tid];
            ((float*)(smem + BNI_OFF))[tid] = g_bni[tid];
            ((float*)(smem + BNH_OFF))[tid] = g_bnh[tid];
            ((float*)(smem + BP_OFF))[tid]  = g_bprime[tid];
        }
        if (tid < 192) ((float*)(smem + WO_OFF))[tid] = Wout[(tid / 3) * 64 + (tid % 3)];
    }
    __syncthreads();

    const float* f_br  = (const float*)(smem + BR_OFF);
    const float* f_bz  = (const float*)(smem + BZ_OFF);
    const float* f_bni = (const float*)(smem + BNI_OFF);
    const float* f_bnh = (const float*)(smem + BNH_OFF);
    const float* f_bp  = (const float*)(smem + BP_OFF);
    const float* f_wcm = (const float*)(smem + WCM_OFF);
    const float* f_wo  = (const float*)(smem + WO_OFF);
    const float bo0 = __ldg(bout + 0), bo1 = __ldg(bout + 1), bo2 = __ldg(bout + 2);

    // stage-A mapping
    const int row  = tid >> 1;          // 0..127
    const int j0m  = (tid & 1) * 32;

    // GEMM mapping
    const int wr0  = wid * 16;          // warp row stripe
    const int g    = lane >> 2;
    const int tid4 = lane & 3;
    // ldmatrix source addresses (byte offsets advance by kstep*32)
    const uint32_t a_row_byte = (uint32_t)(wr0 + (lane & 15)) * (SA * 2) + (uint32_t)(lane >> 4) * 16;
    const uint32_t b_lane_byte = (uint32_t)((lane & 15) & 7) * (SA * 2) + (uint32_t)(((lane & 15) >> 3) & 1) * 16;

    const int ntiles = (Nn + 127) >> 7;
    for (int tile = blockIdx.x; tile < ntiles; tile += gridDim.x) {
        const int nbase = tile << 7;

        // ============ stage A: build X_cat [128][128] bf16 hi/lo ============
        {
            const int gn = nbase + row;
            const bool valid = gn < Nn;
            float a[32];
            if (valid) {
                float c0 = __ldg(&g_ddeg[gn]), c1 = __ldg(&g_ddeg[NNODES + gn]);
                float d0 = (c0 > 0.f) ? 1.f / c0 : 0.f;
                float d1 = (c1 > 0.f) ? 1.f / c1 : 0.f;
#pragma unroll
                for (int q = 0; q < 4; q++) {
                    float4 v = g_agg[(size_t)gn * 4 + q];
                    a[q * 4 + 0] = v.x * d0; a[q * 4 + 1] = v.y * d0;
                    a[q * 4 + 2] = v.z * d0; a[q * 4 + 3] = v.w * d0;
                    float4 w = g_agg[(size_t)(NNODES + gn) * 4 + q];
                    a[16 + q * 4 + 0] = w.x * d1; a[16 + q * 4 + 1] = w.y * d1;
                    a[16 + q * 4 + 2] = w.z * d1; a[16 + q * 4 + 3] = w.w * d1;
                }
            } else {
#pragma unroll
                for (int q = 0; q < 32; q++) a[q] = 0.f;
            }
            float acc[32];
#pragma unroll
            for (int s = 0; s < 32; s++) acc[s] = f_bp[j0m + s];
#pragma unroll
            for (int i2 = 0; i2 < 32; i2++) {
                float av = a[i2];
                const float* w = f_wcm + i2 * 64 + j0m;
#pragma unroll
                for (int s = 0; s < 32; s++) acc[s] += av * w[s];
            }
#pragma unroll
            for (int jp = 0; jp < 32; jp += 2)
                write_a(smem, row, j0m + jp, fmaxf(acc[jp], 0.f), fmaxf(acc[jp + 1], 0.f));
            const float4* hq = (const float4*)(hprev + (size_t)gn * 64 + j0m);
#pragma unroll
            for (int q = 0; q < 8; q++) {
                float4 v = valid ? __ldg(hq + q) : make_float4(0.f, 0.f, 0.f, 0.f);
                write_a(smem, row, 64 + j0m + q * 4,     v.x, v.y);
                write_a(smem, row, 64 + j0m + q * 4 + 2, v.z, v.w);
            }
        }
        __syncthreads();

        // ============ GEMM: D[128][256] = Xcat @ B^T, 3-term bf16 split ============
        float acc[128];
#pragma unroll
        for (int s = 0; s < 128; s++) acc[s] = 0.f;

#pragma unroll
        for (int ks = 0; ks < 8; ks++) {
            uint32_t ah0, ah1, ah2, ah3, al0, al1, al2, al3;
            uint32_t a_addr = sbase + a_row_byte + (uint32_t)ks * 32;
            ldsm4(ah0, ah1, ah2, ah3, a_addr + A_HI_OFF);
            ldsm4(al0, al1, al2, al3, a_addr + A_LO_OFF);
#pragma unroll
            for (int nt = 0; nt < 32; nt++) {
                uint32_t b_addr = sbase + b_lane_byte + (uint32_t)(nt * 8) * (SA * 2)
                                + (uint32_t)ks * 32;
                uint32_t bh0, bh1, bl0, bl1;
                ldsm2(bh0, bh1, b_addr + B_HI_OFF);
                ldsm2(bl0, bl1, b_addr + B_LO_OFF);
                float* c = acc + nt * 4;
                mma16816(c, ah0, ah1, ah2, ah3, bh0, bh1);
                mma16816(c, ah0, ah1, ah2, ah3, bl0, bl1);
                mma16816(c, al0, al1, al2, al3, bh0, bh1);
            }
        }

        // ============ epilogue: GRU combine + store + fused pred ============
#pragma unroll
        for (int rsel = 0; rsel < 2; rsel++) {
            const int lrow = wr0 + g + rsel * 8;
            const int gn = nbase + lrow;
            const bool ev = gn < Nn;
            const int ci = rsel * 2;        // c0,c1 vs c2,c3
            float p0 = 0.f, p1 = 0.f, p2 = 0.f;
#pragma unroll
            for (int nt = 0; nt < 8; nt++) {
                const int jj = nt * 8 + tid4 * 2;
                float2 hp = ev ? __ldg((const float2*)(hprev + (size_t)gn * 64 + jj))
                               : make_float2(0.f, 0.f);
                float res[2];
#pragma unroll
                for (int s = 0; s < 2; s++) {
                    int jc = jj + s;
                    float rv = acc[nt * 4 + ci + s]        + f_br[jc];
                    float zv = acc[(nt + 8) * 4 + ci + s]  + f_bz[jc];
                    float iv = acc[(nt + 16) * 4 + ci + s] + f_bni[jc];
                    float hv = acc[(nt + 24) * 4 + ci + s] + f_bnh[jc];
                    float r = sigf(rv);
                    float z = sigf(zv);
                    float nn = tanhfast(iv + r * hv);
                    float hpv = s ? hp.y : hp.x;
                    res[s] = (1.f - z) * nn + z * hpv;
                    p0 += res[s] * f_wo[jc * 3 + 0];
                    p1 += res[s] * f_wo[jc * 3 + 1];
                    p2 += res[s] * f_wo[jc * 3 + 2];
                }
                if (ev) *(float2*)(out + (size_t)gn * 64 + jj) = make_float2(res[0], res[1]);
            }
#pragma unroll
            for (int m2 = 1; m2 < 4; m2 <<= 1) {
                p0 += __shfl_xor_sync(0xffffffffu, p0, m2);
                p1 += __shfl_xor_sync(0xffffffffu, p1, m2);
                p2 += __shfl_xor_sync(0xffffffffu, p2, m2);
            }
            if (tid4 == 0 && ev) {
                float* pp = out + (size_t)Nn * 64 + (size_t)gn * 3;
                pp[0] = p0 + bo0; pp[1] = p1 + bo1; pp[2] = p2 + bo2;
            }
        }
        __syncthreads();   // A smem reuse next tile
    }
}

// ---------------- launch ----------------
extern "C" void kernel_launch(void* const* d_in, const int* in_sizes, int n_in,
                              void* d_out, int out_size) {
    const float* x     = (const float*)d_in[0];
    const float* hprev = (const float*)d_in[1];
    const int*   en    = (const int*)d_in[2];
    const int*   eh    = (const int*)d_in[3];
    const int*   ea    = (const int*)d_in[4];
    const float* Wconv = (const float*)d_in[5];
    const float* bconv = (const float*)d_in[6];
    const float* Wmix  = (const float*)d_in[7];
    const float* bmix  = (const float*)d_in[8];
    const float* Wih   = (const float*)d_in[9];
    const float* Whh   = (const float*)d_in[10];
    const float* bih   = (const float*)d_in[11];
    const float* bhh   = (const float*)d_in[12];
    const float* Wout  = (const float*)d_in[13];
    const float* bout  = (const float*)d_in[14];
    float* out = (float*)d_out;

    (void)in_sizes; (void)n_in; (void)out_size;

    k_pre<<<10098, 256>>>(Wconv, bconv, Wmix, bmix, Wih, Whh, bih, bhh);
    k_scat1<<<31250, 256>>>(en, eh, ea, (const float4*)x);
    k_scat2<<<31250, 256>>>(en, eh, ea);

    cudaFuncSetAttribute(k_gru, cudaFuncAttributeMaxDynamicSharedMemorySize, SMEM_TOTAL);
    k_gru<<<148, 256, SMEM_TOTAL>>>(hprev, Wout, bout, out, NNODES);
}